// round 17
// baseline (speedup 1.0000x reference)
#include <cuda_runtime.h>
#include <cstdint>

#define B_TOTAL 65536
#define HDIM    256

// ---------------- scratch (allocation-free) ----------------
__device__ float    g_h [2ULL * B_TOTAL * HDIM];   // exact fp32 hidden (ping-pong)
__device__ unsigned g_ht[2ULL * B_TOTAL * HDIM];   // tf32-bit hidden, PAIRED layout
__device__ unsigned g_xt[(size_t)B_TOTAL * HDIM];  // tf32-bit x, PAIRED layout
// weights pre-converted + pre-tiled + pair-packed:
// [u][jc4][s16][gate3][rr16][n64 pairs = 128 words]
#define WT_PER_UNIT (4 * 16 * 48 * 128)
__device__ unsigned g_wt[8ULL * WT_PER_UNIT];

// ---------------- smem ring (4 stages, A+W per k32 step) ----------------
#define A_RS   40                        // A row stride words (16 pairs + 8 pad)
#define ASTG   (128 * A_RS)              // 5120 words
#define W_RS   136                       // W row stride words (64 pairs + 8 pad)
#define WGATE  (16 * W_RS)               // 2176 words per gate
#define STG_WORDS (ASTG + 3 * WGATE)     // 11648
#define SMEM_WORDS (4 * STG_WORDS)       // 46592
#define SMEM_BYTES (SMEM_WORDS * 4)      // 186368 B

__device__ __forceinline__ unsigned f2tf(float f) {
    unsigned u;
    asm("cvt.rna.tf32.f32 %0, %1;" : "=r"(u) : "f"(f));
    return u;
}
__device__ __forceinline__ uint32_t smem_u32(const void* p) {
    uint32_t a;
    asm("{ .reg .u64 t; cvta.to.shared.u64 t, %1; cvt.u32.u64 %0, t; }"
        : "=r"(a) : "l"(p));
    return a;
}
#define CP16(dst_u32, src_ptr) \
    asm volatile("cp.async.cg.shared.global [%0], [%1], 16;" \
                 :: "r"(dst_u32), "l"(src_ptr))
#define CP_COMMIT()  asm volatile("cp.async.commit_group;" ::: "memory")
#define CP_WAIT0()   asm volatile("cp.async.wait_group 0;" ::: "memory")

__device__ __forceinline__ void mma_tf32(float c[4],
                                         unsigned a0, unsigned a1, unsigned a2, unsigned a3,
                                         unsigned b0, unsigned b1) {
    asm volatile(
        "mma.sync.aligned.m16n8k8.row.col.f32.tf32.tf32.f32 "
        "{%0,%1,%2,%3}, {%4,%5,%6,%7}, {%8,%9}, {%0,%1,%2,%3};\n"
        : "+f"(c[0]), "+f"(c[1]), "+f"(c[2]), "+f"(c[3])
        : "r"(a0), "r"(a1), "r"(a2), "r"(a3), "r"(b0), "r"(b1));
}

// paired offset of feature k within a 256-wide row: chunk*32 + pair*2 + slot
__device__ __forceinline__ int pair_off(int k) {
    int c = k >> 5, w = k & 31, g = w >> 3, d = w & 7;
    return c * 32 + (g * 4 + (d & 3)) * 2 + (d >> 2);
}

// One GRU cell.  Grid (4 j-chunks of 64, 512 batch tiles of 128), 512 threads,
// 16 warps 4(M)x4(N), warp tile 32m x 16n.  Unified 16-step k32 ring over
// [x|h]: A+W co-staged per stage (4-stage ring), barrier every 2 steps,
// all fragments fetched as (k,k+4) LDS.64 pairs from pre-packed layouts.
__global__ void __launch_bounds__(512)
gru_unit(const unsigned* __restrict__ xt, const float* __restrict__ hprev,
         const unsigned* __restrict__ htprev,
         float* __restrict__ hout, unsigned* __restrict__ htout,
         const unsigned* __restrict__ wt,           // this unit's g_wt slice
         const float* __restrict__ bih, const float* __restrict__ bhh) {
    extern __shared__ unsigned smem[];
    const uint32_t sbase = smem_u32(smem);

    const int tid  = threadIdx.x;
    const int lane = tid & 31;
    const int wid  = tid >> 5;
    const int grp  = lane >> 2;
    const int tg   = lane & 3;
    const int wm   = wid & 3;                // rows 32*wm
    const int wn   = wid >> 2;               // cols 16*wn
    const int jc   = blockIdx.x;
    const int j0   = jc * 64;
    const int b0   = blockIdx.y * 128;

    float C[4][2][2][4];                     // [r,z,n_i,n_h][mt][t][frag]
#pragma unroll
    for (int a = 0; a < 4; a++)
#pragma unroll
        for (int mt = 0; mt < 2; mt++)
#pragma unroll
            for (int t = 0; t < 2; t++)
#pragma unroll
                for (int c = 0; c < 4; c++) C[a][mt][t][c] = 0.f;

    // ---- stage issue: A chunk (1024 granules) + W chunk (1536 granules) ----
    auto issueStage = [&](int s2) {
        const int      stg  = (s2 & 3) * STG_WORDS;
        const unsigned* asrc = ((s2 >> 3) ? htprev : xt) + (size_t)b0 * 256
                             + (s2 & 7) * 32;
#pragma unroll
        for (int i = 0; i < 2; i++) {
            int g = tid + i * 512;           // 0..1023
            int row = g >> 3, q = g & 7;
            CP16(sbase + (uint32_t)(stg + row * A_RS + q * 4) * 4,
                 asrc + (size_t)row * 256 + q * 4);
        }
        const unsigned* wsrc = wt + (size_t)(jc * 16 + s2) * 48 * 128;
#pragma unroll
        for (int i = 0; i < 3; i++) {
            int g = tid + i * 512;           // 0..1535
            int row = g >> 5, q = g & 31;    // row 0..47, q 0..31
            CP16(sbase + (uint32_t)(stg + ASTG + (row >> 4) * WGATE
                                    + (row & 15) * W_RS + q * 4) * 4,
                 wsrc + (size_t)row * 128 + q * 4);
        }
    };

    // ---- one k32 compute step ----
    const int rowa0 = 32 * wm + grp;
    auto stepCompute = [&](int s) {
        const int phase = s >> 3;
        const unsigned* stg = smem + (s & 3) * STG_WORDS;
#pragma unroll
        for (int gsub = 0; gsub < 4; gsub++) {
            const int pidx = (gsub * 4 + tg) * 2;
            unsigned a0[2], a1[2], a2[2], a3[2];
#pragma unroll
            for (int mt = 0; mt < 2; mt++) {
                int r0 = rowa0 + 16 * mt;
                uint2 p0 = *reinterpret_cast<const uint2*>(&stg[r0 * A_RS + pidx]);
                uint2 p1 = *reinterpret_cast<const uint2*>(&stg[(r0 + 8) * A_RS + pidx]);
                a0[mt] = p0.x; a2[mt] = p0.y;
                a1[mt] = p1.x; a3[mt] = p1.y;
            }
#pragma unroll
            for (int gate = 0; gate < 3; gate++) {
                const int ai = (gate == 2) ? (2 + phase) : gate;
                const unsigned* wb = stg + ASTG + gate * WGATE + (gsub * 4 + tg) * W_RS;
#pragma unroll
                for (int t = 0; t < 2; t++) {
                    int n = wn * 16 + t * 8 + grp;
                    uint2 pB = *reinterpret_cast<const uint2*>(&wb[n * 2]);
#pragma unroll
                    for (int mt = 0; mt < 2; mt++)
                        mma_tf32(C[ai][mt][t],
                                 a0[mt], a1[mt], a2[mt], a3[mt], pB.x, pB.y);
                }
            }
        }
    };

    // prologue: stages 0,1
    issueStage(0);
    issueStage(1);
    CP_COMMIT();
    CP_WAIT0();
    __syncthreads();

    // 8 super-steps of 2 k32 steps each
    for (int S = 0; S < 8; S++) {
        if (S < 7) {
            issueStage(2 * S + 2);
            issueStage(2 * S + 3);
            CP_COMMIT();
        }
        stepCompute(2 * S);
        stepCompute(2 * S + 1);
        CP_WAIT0();
        if (S < 7) __syncthreads();
    }

    // ---- fused gate epilogue: exact fp32 h_prev; emit paired tf32 h ----
#pragma unroll
    for (int t = 0; t < 2; t++) {
        int col0 = j0 + wn * 16 + t * 8 + 2 * tg;
#pragma unroll
        for (int cc = 0; cc < 2; cc++) {
            int j = col0 + cc;
            float br  = bih[j]       + bhh[j];
            float bz  = bih[256 + j] + bhh[256 + j];
            float bni = bih[512 + j];
            float bnh = bhh[512 + j];
            int   po  = pair_off(j);
#pragma unroll
            for (int mt = 0; mt < 2; mt++) {
                int mrow = b0 + 32 * wm + 16 * mt + grp;
#pragma unroll
                for (int rr = 0; rr < 2; rr++) {
                    int row = mrow + rr * 8;
                    int ci  = rr * 2 + cc;
                    float vr = C[0][mt][t][ci] + br;
                    float vz = C[1][mt][t][ci] + bz;
                    float n1 = C[2][mt][t][ci] + bni;
                    float n2 = C[3][mt][t][ci] + bnh;
                    float r  = 1.f / (1.f + __expf(-vr));
                    float z  = 1.f / (1.f + __expf(-vz));
                    float n  = tanhf(n1 + r * n2);
                    float hp = hprev[(size_t)row * 256 + j];
                    float hv = (1.f - z) * n + z * hp;
                    hout [(size_t)row * 256 + j]  = hv;
                    htout[(size_t)row * 256 + po] = f2tf(hv);
                }
            }
        }
    }
}

// ---- once-per-launch converters ----
__global__ void conv_w(const float* __restrict__ Wih, const float* __restrict__ Whh) {
    const size_t total = 8ULL * WT_PER_UNIT;
    for (size_t i = blockIdx.x * (size_t)blockDim.x + threadIdx.x; i < total;
         i += (size_t)gridDim.x * blockDim.x) {
        int n2   = (int)(i & 127);
        int n    = n2 >> 1, slot = n2 & 1;
        size_t r7 = i >> 7;
        int row  = (int)(r7 % 48);          // gate*16 + rr
        int rr   = row & 15, gate = row >> 4;
        size_t r8 = r7 / 48;
        int s    = (int)(r8 & 15);
        int jc   = (int)((r8 >> 4) & 3);
        int u    = (int)(r8 >> 6);
        int gsub = rr >> 2, d3 = rr & 3;
        int kk   = gsub * 8 + slot * 4 + d3;
        int ph   = s >> 3;
        int k    = (s & 7) * 32 + kk;
        const float* W = (ph ? Whh : Wih) + (size_t)u * 768 * 256;
        g_wt[i] = f2tf(W[((size_t)gate * 256 + jc * 64 + n) * 256 + k]);
    }
}
__global__ void conv_x(const float* __restrict__ x) {
    const size_t total = (size_t)B_TOTAL * HDIM;
    for (size_t i = blockIdx.x * (size_t)blockDim.x + threadIdx.x; i < total;
         i += (size_t)gridDim.x * blockDim.x) {
        int ww = (int)(i & 255);
        int c = ww >> 5, t2 = ww & 31;
        int p = t2 >> 1, slot = t2 & 1;
        int k = c * 32 + (p >> 2) * 8 + slot * 4 + (p & 3);
        g_xt[i] = f2tf(x[(i & ~(size_t)255) + k]);
    }
}
__global__ void init_h(const float* __restrict__ h0, float* __restrict__ hb,
                       unsigned* __restrict__ htb) {
    const size_t total = (size_t)B_TOTAL * HDIM;
    for (size_t i = blockIdx.x * (size_t)blockDim.x + threadIdx.x; i < total;
         i += (size_t)gridDim.x * blockDim.x) {
        hb[i] = h0[i & 255];
        int ww = (int)(i & 255);
        int c = ww >> 5, t2 = ww & 31;
        int p = t2 >> 1, slot = t2 & 1;
        int k = c * 32 + (p >> 2) * 8 + slot * 4 + (p & 3);
        htb[i] = f2tf(h0[k]);
    }
}

extern "C" void kernel_launch(void* const* d_in, const int* in_sizes, int n_in,
                              void* d_out, int out_size) {
    const float* x   = (const float*)d_in[0];
    const float* Wih = (const float*)d_in[1];
    const float* Whh = (const float*)d_in[2];
    const float* bih = (const float*)d_in[3];
    const float* bhh = (const float*)d_in[4];
    const float* h0  = (const float*)d_in[5];
    float* out = (float*)d_out;

    float *hb; unsigned *htb, *xtb, *wtb;
    cudaGetSymbolAddress((void**)&hb,  g_h);
    cudaGetSymbolAddress((void**)&htb, g_ht);
    cudaGetSymbolAddress((void**)&xtb, g_xt);
    cudaGetSymbolAddress((void**)&wtb, g_wt);
    float*    h0b = hb;                 float*    h1b = hb  + (size_t)B_TOTAL * HDIM;
    unsigned* t0b = htb;                unsigned* t1b = htb + (size_t)B_TOTAL * HDIM;

    cudaFuncSetAttribute(gru_unit, cudaFuncAttributeMaxDynamicSharedMemorySize, SMEM_BYTES);

    conv_w<<<4096, 256>>>(Wih, Whh);
    conv_x<<<2048, 256>>>(x);
    init_h<<<1024, 256>>>(h0, h0b, t0b);

    for (int u = 0; u < 8; u++) {
        const float*    hsrc = (u & 1) ? h1b : h0b;
        const unsigned* tsrc = (u & 1) ? t1b : t0b;
        float*    hdst = (u == 7) ? out : ((u & 1) ? h0b : h1b);
        unsigned* tdst = (u & 1) ? t0b : t1b;    // scratch; unused after u=7
        gru_unit<<<dim3(4, 512), 512, SMEM_BYTES>>>(
            xtb, hsrc, tsrc, hdst, tdst,
            wtb + (size_t)u * WT_PER_UNIT,
            bih + (size_t)u * 768, bhh + (size_t)u * 768);
    }
}